// round 1
// baseline (speedup 1.0000x reference)
#include <cuda_runtime.h>
#include <cuda_bf16.h>
#include <cstdint>

// GATLayer: h = x@W; a_src/a_dst dots; edge softmax (shift-invariant, max pass
// elided since |alpha| is O(1)); weighted scatter-sum; bias + ELU.
//
// N = 50000, F_IN = 256, HEADS = 8, C = 32, E = 800000 (+N self loops).

#define F_IN   256
#define F_OUT  256
#define HEADS  8
#define MAXN   50048

// -------- scratch (__device__ globals; no allocation allowed) --------
__device__ __align__(16) float g_h[(size_t)MAXN * F_OUT];     // ~51.25 MB
__device__ __align__(16) float g_asrc[(size_t)MAXN * HEADS];
__device__ __align__(16) float g_adst[(size_t)MAXN * HEADS];
__device__ __align__(16) float g_denom[(size_t)MAXN * HEADS];

// -------- vector global reduction (sm_90+) --------
__device__ __forceinline__ void red_add_v4(float* p, float4 v) {
    asm volatile("red.global.add.v4.f32 [%0], {%1, %2, %3, %4};"
                 :: "l"(p), "f"(v.x), "f"(v.y), "f"(v.z), "f"(v.w)
                 : "memory");
}

// ============================================================================
// Kernel 1: GEMM  g_h = x @ W     (64x64 tile, BK=16, 4x4 microtile)
// ============================================================================
#define BM 64
#define BN 64
#define BK 16
__global__ __launch_bounds__(256) void gemm_kernel(
    const float* __restrict__ X, const float* __restrict__ W, int N)
{
    __shared__ float As[BK][BM];
    __shared__ float Bs[BK][BN];

    const int tid = threadIdx.x;                 // 0..255
    const int block_row = blockIdx.x * BM;
    const int block_col = blockIdx.y * BN;
    const int ty = tid >> 4;                     // 0..15
    const int tx = tid & 15;                     // 0..15

    // A load mapping: thread -> one float4 of X per k-tile
    const int arow  = tid >> 2;                  // 0..63
    const int acol4 = (tid & 3) << 2;            // 0,4,8,12
    // B load mapping: thread -> one float4 of W per k-tile
    const int brow  = tid >> 4;                  // 0..15
    const int bcol4 = (tid & 15) << 2;           // 0..60

    const bool arow_ok = (block_row + arow) < N;

    float acc[4][4];
#pragma unroll
    for (int i = 0; i < 4; i++)
#pragma unroll
        for (int j = 0; j < 4; j++) acc[i][j] = 0.f;

    for (int kt = 0; kt < F_IN; kt += BK) {
        float4 a4 = make_float4(0.f, 0.f, 0.f, 0.f);
        if (arow_ok)
            a4 = *(const float4*)&X[(size_t)(block_row + arow) * F_IN + kt + acol4];
        As[acol4 + 0][arow] = a4.x;
        As[acol4 + 1][arow] = a4.y;
        As[acol4 + 2][arow] = a4.z;
        As[acol4 + 3][arow] = a4.w;

        *(float4*)&Bs[brow][bcol4] =
            *(const float4*)&W[(size_t)(kt + brow) * F_OUT + block_col + bcol4];
        __syncthreads();

#pragma unroll
        for (int k = 0; k < BK; k++) {
            float4 av = *(const float4*)&As[k][ty << 2];
            float4 bv = *(const float4*)&Bs[k][tx << 2];
            float a_[4] = {av.x, av.y, av.z, av.w};
            float b_[4] = {bv.x, bv.y, bv.z, bv.w};
#pragma unroll
            for (int i = 0; i < 4; i++)
#pragma unroll
                for (int j = 0; j < 4; j++)
                    acc[i][j] = fmaf(a_[i], b_[j], acc[i][j]);
        }
        __syncthreads();
    }

#pragma unroll
    for (int i = 0; i < 4; i++) {
        int row = block_row + (ty << 2) + i;
        if (row < N) {
            float4 v = make_float4(acc[i][0], acc[i][1], acc[i][2], acc[i][3]);
            *(float4*)&g_h[(size_t)row * F_OUT + block_col + (tx << 2)] = v;
        }
    }
}

// ============================================================================
// Kernel 2: per-node attention dots (+ zero denom)
//   block = one node, 256 threads; warp w == head w (32 channels)
// ============================================================================
__global__ __launch_bounds__(256) void attdot_kernel(
    const float* __restrict__ att_src, const float* __restrict__ att_dst)
{
    const int n = blockIdx.x;
    const int tid = threadIdx.x;
    const int lane = tid & 31;
    const int w = tid >> 5;          // head index

    float hv = g_h[(size_t)n * F_OUT + tid];
    float s = hv * att_src[tid];     // att_src flat [8*32] matches tid layout
    float d = hv * att_dst[tid];
#pragma unroll
    for (int o = 16; o > 0; o >>= 1) {
        s += __shfl_down_sync(0xffffffffu, s, o);
        d += __shfl_down_sync(0xffffffffu, d, o);
    }
    if (lane == 0) {
        g_asrc[n * HEADS + w] = s;
        g_adst[n * HEADS + w] = d;
        g_denom[n * HEADS + w] = 0.f;
    }
}

// ============================================================================
// Kernel 3: softmax denominators. One thread per edge (incl. self loops).
//   alpha_h = leaky_relu(a_src[src,h] + a_dst[dst,h]); denom[dst,h] += exp(alpha_h)
// ============================================================================
__global__ __launch_bounds__(256) void edge_denom_kernel(
    const int* __restrict__ ei, int E, int N)
{
    int e = blockIdx.x * blockDim.x + threadIdx.x;
    int total = E + N;
    if (e >= total) return;
    int src, dst;
    if (e < E) { src = ei[e]; dst = ei[E + e]; }
    else       { src = dst = e - E; }

    float4 s0 = *(const float4*)&g_asrc[src * HEADS];
    float4 s1 = *(const float4*)&g_asrc[src * HEADS + 4];
    float4 d0 = *(const float4*)&g_adst[dst * HEADS];
    float4 d1 = *(const float4*)&g_adst[dst * HEADS + 4];

    float a[8] = {s0.x + d0.x, s0.y + d0.y, s0.z + d0.z, s0.w + d0.w,
                  s1.x + d1.x, s1.y + d1.y, s1.z + d1.z, s1.w + d1.w};
#pragma unroll
    for (int h = 0; h < 8; h++) {
        float v = a[h];
        v = v > 0.f ? v : 0.2f * v;   // leaky relu
        a[h] = __expf(v);
    }
    red_add_v4(&g_denom[dst * HEADS],     make_float4(a[0], a[1], a[2], a[3]));
    red_add_v4(&g_denom[dst * HEADS + 4], make_float4(a[4], a[5], a[6], a[7]));
}

// ============================================================================
// Kernel 4: weighted aggregation. One warp per edge.
//   lane owns 8 contiguous channels -> head = lane/4. Two red.v4 per lane.
// ============================================================================
__global__ __launch_bounds__(256) void edge_agg_kernel(
    const int* __restrict__ ei, int E, int N, float* __restrict__ out)
{
    int gw = (blockIdx.x * blockDim.x + threadIdx.x) >> 5;  // global warp id
    int lane = threadIdx.x & 31;
    int total = E + N;
    if (gw >= total) return;

    int src, dst;
    if (gw < E) { src = ei[gw]; dst = ei[E + gw]; }
    else        { src = dst = gw - E; }

    int h = lane >> 2;                                       // head of my 8 chans
    float a = g_asrc[src * HEADS + h] + g_adst[dst * HEADS + h];
    a = a > 0.f ? a : 0.2f * a;
    float wgt = __expf(a) / g_denom[dst * HEADS + h];

    const float4* hp = (const float4*)&g_h[(size_t)src * F_OUT + lane * 8];
    float4 v0 = hp[0], v1 = hp[1];
    v0.x *= wgt; v0.y *= wgt; v0.z *= wgt; v0.w *= wgt;
    v1.x *= wgt; v1.y *= wgt; v1.z *= wgt; v1.w *= wgt;

    float* op = &out[(size_t)dst * F_OUT + lane * 8];
    red_add_v4(op, v0);
    red_add_v4(op + 4, v1);
}

// ============================================================================
// Kernel 5: out = elu(out + bias)
// ============================================================================
__global__ __launch_bounds__(256) void elu_bias_kernel(
    float* __restrict__ out, const float* __restrict__ bias, int total4)
{
    int i = blockIdx.x * blockDim.x + threadIdx.x;
    if (i >= total4) return;
    float4 v = ((float4*)out)[i];
    const float4 b = ((const float4*)bias)[i & 63];          // 256/4 = 64 f4 per row
    v.x += b.x; v.y += b.y; v.z += b.z; v.w += b.w;
    v.x = v.x > 0.f ? v.x : expm1f(v.x);
    v.y = v.y > 0.f ? v.y : expm1f(v.y);
    v.z = v.z > 0.f ? v.z : expm1f(v.z);
    v.w = v.w > 0.f ? v.w : expm1f(v.w);
    ((float4*)out)[i] = v;
}

// ============================================================================
extern "C" void kernel_launch(void* const* d_in, const int* in_sizes, int n_in,
                              void* d_out, int out_size)
{
    const float* x       = (const float*)d_in[0];
    const int*   ei      = (const int*)  d_in[1];
    const float* W       = (const float*)d_in[2];
    const float* att_src = (const float*)d_in[3];
    const float* att_dst = (const float*)d_in[4];
    const float* bias    = (const float*)d_in[5];
    float* out = (float*)d_out;

    const int N = in_sizes[0] / F_IN;     // 50000
    const int E = in_sizes[1] / 2;        // 800000
    const int total = E + N;              // with self loops

    dim3 ggrid((N + BM - 1) / BM, F_OUT / BN);
    gemm_kernel<<<ggrid, 256>>>(x, W, N);

    attdot_kernel<<<N, 256>>>(att_src, att_dst);

    cudaMemsetAsync(d_out, 0, (size_t)out_size * sizeof(float));

    edge_denom_kernel<<<(total + 255) / 256, 256>>>(ei, E, N);

    int agg_blocks = (total + 7) / 8;     // 8 warps (edges) per 256-thread block
    edge_agg_kernel<<<agg_blocks, 256>>>(ei, E, N, out);

    int total4 = N * (F_OUT / 4);
    elu_bias_kernel<<<(total4 + 255) / 256, 256>>>(out, bias, total4);
}